// round 15
// baseline (speedup 1.0000x reference)
#include <cuda_runtime.h>

#define NQ      12
#define THREADS 256
#define NREG    8           // ull (amplitude pairs) per thread: 2048/256
#define STSZ    2176        // padded pair slots: max P(2047)=2174
typedef unsigned long long ull;

#define SGN2 0x8000000080000000ULL

__device__ __forceinline__ ull pk(float lo, float hi) {
    ull r; asm("mov.b64 %0, {%1, %2};" : "=l"(r) : "f"(lo), "f"(hi)); return r;
}
__device__ __forceinline__ void upk(ull a, float& lo, float& hi) {
    asm("mov.b64 {%0, %1}, %2;" : "=f"(lo), "=f"(hi) : "l"(a));
}
__device__ __forceinline__ ull fma2(ull a, ull b, ull c) {
    ull d; asm("fma.rn.f32x2 %0, %1, %2, %3;" : "=l"(d) : "l"(a), "l"(b), "l"(c)); return d;
}
__device__ __forceinline__ ull mul2(ull a, ull b) {
    ull d; asm("mul.rn.f32x2 %0, %1, %2;" : "=l"(d) : "l"(a), "l"(b)); return d;
}

// cross-register tan-form butterfly on register bit rb
#define XGATE(T2, RB)                                                       \
    {                                                                       \
        const ull t2  = (T2);                                               \
        const ull nt2 = t2 ^ SGN2;                                          \
        _Pragma("unroll")                                                   \
        for (int m = 0; m < 4; m++) {                                       \
            const int low = (1 << (RB)) - 1;                                \
            const int j0_ = ((m & ~low) << 1) | (m & low);                  \
            const int j1_ = j0_ | (1 << (RB));                              \
            ull a0 = v[j0_];                                                \
            v[j0_] = fma2(nt2, v[j1_], a0);                                 \
            v[j1_] = fma2(t2,  a0,   v[j1_]);                               \
        }                                                                   \
    }

__global__ __launch_bounds__(THREADS, 6)
void qc_kernel(const float* __restrict__ x,
               const float* __restrict__ th,
               float* __restrict__ out)
{
    __shared__ ull st2[STSZ];
    __shared__ float enc_c[NQ], enc_s[NQ];
    __shared__ ull th_t2[2][NQ];            // packed (tan, tan)
    __shared__ float cosv[2 * NQ];
    __shared__ float red[(THREADS / 32) * NQ];

    float* stf = (float*)st2;               // float view for the scatter

    const int b    = blockIdx.x;
    const int t    = threadIdx.x;
    const int lane = t & 31;

    // ownership bases (ull slots); pad P(p) = p + (p>>4); both conflict-free (R14-verified)
    const int baseA = 8 * t + (t >> 1);                                   // + j
    const int baseD = t + (t >> 4);                                       // + 272*j

    // ---- angle precompute ----
    if (t < NQ) {
        float s_, c_;
        sincosf(0.5f * x[b * NQ + t], &s_, &c_);
        enc_c[t] = c_; enc_s[t] = s_;
    } else if (t >= 32 && t < 32 + 2 * NQ) {
        int k = t - 32;
        float s_, c_;
        sincosf(0.5f * th[k], &s_, &c_);
        float tg = s_ / c_;
        th_t2[k / NQ][k % NQ] = pk(tg, tg);
        cosv[k] = c_;
    }
    __syncthreads();

    // ---- product state in A-ownership: pair p = 8t + j; halves = qubit 0 ----
    // p bits 0-2 = j -> qubits 1-3 ; p bits 3-10 = t -> qubits 4-11
    ull v[NREG];
    {
        float ht = (t & 1) ? enc_s[4] : enc_c[4];
        #pragma unroll
        for (int i = 1; i < 8; i++)
            ht *= ((t >> i) & 1) ? enc_s[4 + i] : enc_c[4 + i];
        ull hcs = pk(ht * enc_c[0], ht * enc_s[0]);
        float g01[4];
        #pragma unroll
        for (int m = 0; m < 4; m++)
            g01[m] = ((m & 1) ? enc_s[1] : enc_c[1]) * ((m & 2) ? enc_s[2] : enc_c[2]);
        #pragma unroll
        for (int j = 0; j < NREG; j++) {
            float jf = g01[j & 3] * ((j & 4) ? enc_s[3] : enc_c[3]);
            v[j] = mul2(hcs, pk(jf, jf));
        }
    }

    // scatter / sign constants (prefix-xor over t's 8 bits)  [R14-verified]
    unsigned yt = (unsigned)t; yt ^= yt << 1; yt ^= yt << 2; yt ^= yt << 4;
    const int pt = (yt >> 7) & 1;             // parity(t)
    const int Zt = t ^ (int)((yt << 1) & 0x1FE) ^ (pt << 9) ^ (pt << 10);

    // ---- variational layers (tan-form, cosines deferred) ----
    #pragma unroll
    for (int layer = 0; layer < 2; layer++) {
        const ull* T = th_t2[layer];

        // q0: register halves (scalar tan butterfly)
        {
            float tg, dum; upk(T[0], tg, dum);
            #pragma unroll
            for (int j = 0; j < NREG; j++) {
                float lo, hi; upk(v[j], lo, hi);
                float nlo = fmaf(-tg, hi, lo);
                float nhi = fmaf( tg, lo, hi);
                v[j] = pk(nlo, nhi);
            }
        }
        // q1-3: register-bit butterflies
        XGATE(T[1], 0) XGATE(T[2], 1) XGATE(T[3], 2)

        // q4-8: lane-bit butterflies via warp shuffle (lane bit i = qubit 4+i)
        // coeff uniform per thread: bit=1 -> +tan, bit=0 -> -tan
        #pragma unroll
        for (int i = 0; i < 5; i++) {
            const ull t2 = T[4 + i];
            const ull cf = ((lane >> i) & 1) ? t2 : (t2 ^ SGN2);
            #pragma unroll
            for (int j = 0; j < NREG; j++) {
                ull o = __shfl_xor_sync(0xFFFFFFFFu, v[j], 1 << i);
                v[j] = fma2(cf, o, v[j]);
            }
        }

        // single transpose A -> D (q9-11 become reg bits)
        #pragma unroll
        for (int j = 0; j < NREG; j++) st2[baseA + j] = v[j];
        __syncthreads();
        #pragma unroll
        for (int j = 0; j < NREG; j++) v[j] = st2[baseD + 272 * j];

        // q9-11: register-bit butterflies in D-ownership
        XGATE(T[9], 0) XGATE(T[10], 1) XGATE(T[11], 2)

        if (layer == 0) {
            // CNOT ring in pair space: d0 = p ^ correction, d1 = d0 ^ 0x7FF,
            // halves land at position pt ^ parity(j)   [R14-verified]
            __syncthreads();                           // all D reads done
            #pragma unroll
            for (int j = 0; j < NREG; j++) {
                const int j0 = j & 1, j1 = (j >> 1) & 1, j2 = (j >> 2) & 1;
                const int Cj = (j << 8) ^ (j0 << 9) ^ ((j0 ^ j1) << 10);
                const int pj = j0 ^ j1 ^ j2;
                int d0 = Zt ^ Cj;
                int d1 = d0 ^ 0x7FF;
                int hp = pt ^ pj;
                float lo, hi; upk(v[j], lo, hi);
                stf[2 * (d0 + (d0 >> 4)) + hp] = lo;
                stf[2 * (d1 + (d1 >> 4)) + hp] = hi;
            }
            __syncthreads();
            #pragma unroll
            for (int j = 0; j < NREG; j++) v[j] = st2[baseA + j];
        }
        // layer 1: trailing ring folded into expectation signs
    }

    // ---- expectations in D-ownership (p = t + 256j, halves = qubit 0) [R14-verified] ----
    float Tacc = 0.f, D = 0.f, S1 = 0.f, S3 = 0.f, S7 = 0.f;
    #pragma unroll
    for (int j = 0; j < NREG; j++) {
        float lo, hi; upk(v[j], lo, hi);
        float l2 = lo * lo, h2 = hi * hi;
        float sum = l2 + h2, dif = l2 - h2;
        int pj = __popc(j) & 1;
        Tacc += pj ? -sum : sum;
        D    += dif;
        S1   += (j & 1) ? -dif : dif;
        S3   += (__popc(j & 3) & 1) ? -dif : dif;
        S7   += pj ? -dif : dif;
    }

    float acc[NQ];
    acc[0] = pt ? -Tacc : Tacc;
    #pragma unroll
    for (int q = 1; q < 9; q++) {
        int c = __popc(t & ((1 << q) - 1)) & 1;
        acc[q] = c ? -D : D;
    }
    acc[9]  = pt ? -S1 : S1;
    acc[10] = pt ? -S3 : S3;
    acc[11] = pt ? -S7 : S7;

    #pragma unroll
    for (int q = 0; q < NQ; q++) {
        #pragma unroll
        for (int off = 16; off; off >>= 1)
            acc[q] += __shfl_down_sync(0xFFFFFFFFu, acc[q], off);
    }
    const int w = t >> 5;
    if (lane == 0) {
        #pragma unroll
        for (int q = 0; q < NQ; q++) red[w * NQ + q] = acc[q];
    }
    __syncthreads();
    if (t < NQ) {
        float r = 0.0f;
        #pragma unroll
        for (int w2 = 0; w2 < THREADS / 32; w2++) r += red[w2 * NQ + t];
        float cs = cosv[0];
        #pragma unroll
        for (int k = 1; k < 2 * NQ; k++) cs *= cosv[k];
        out[b * NQ + t] = r * cs * cs;
    }
}

extern "C" void kernel_launch(void* const* d_in, const int* in_sizes, int n_in,
                              void* d_out, int out_size)
{
    const float* x  = (const float*)d_in[0];   // (1024, 12) float32
    const float* th = (const float*)d_in[1];   // (2, 12)    float32
    float* o = (float*)d_out;                  // (1024, 12) float32
    (void)in_sizes; (void)n_in; (void)out_size;
    qc_kernel<<<1024, THREADS>>>(x, th, o);
}

// round 16
// speedup vs baseline: 1.0243x; 1.0243x over previous
#include <cuda_runtime.h>

#define NQ      12
#define THREADS 256
#define NREG    16          // ull per thread: 4096 elements / 256 threads (2 items packed)
#define STSZ    4352        // padded: max M(4095) = 4350
typedef unsigned long long ull;

#define SGN2 0x8000000080000000ULL

__device__ __forceinline__ ull pk(float lo, float hi) {
    ull r; asm("mov.b64 %0, {%1, %2};" : "=l"(r) : "f"(lo), "f"(hi)); return r;
}
__device__ __forceinline__ void upk(ull a, float& lo, float& hi) {
    asm("mov.b64 {%0, %1}, %2;" : "=f"(lo), "=f"(hi) : "l"(a));
}
__device__ __forceinline__ ull fma2(ull a, ull b, ull c) {
    ull d; asm("fma.rn.f32x2 %0, %1, %2, %3;" : "=l"(d) : "l"(a), "l"(b), "l"(c)); return d;
}
__device__ __forceinline__ ull mul2(ull a, ull b) {
    ull d; asm("mul.rn.f32x2 %0, %1, %2;" : "=l"(d) : "l"(a), "l"(b)); return d;
}
__device__ __forceinline__ ull add2(ull a, ull b) {
    ull d; asm("add.rn.f32x2 %0, %1, %2;" : "=l"(d) : "l"(a), "l"(b)); return d;
}

// tan-form butterfly over register bit rb (16 ull regs, 8 pairs)
#define XGATE(T2, RB)                                                       \
    {                                                                       \
        const ull t2  = (T2);                                               \
        const ull nt2 = t2 ^ SGN2;                                          \
        _Pragma("unroll")                                                   \
        for (int m = 0; m < 8; m++) {                                       \
            const int low = (1 << (RB)) - 1;                                \
            const int j0_ = ((m & ~low) << 1) | (m & low);                  \
            const int j1_ = j0_ | (1 << (RB));                              \
            ull a0 = v[j0_];                                                \
            v[j0_] = fma2(nt2, v[j1_], a0);                                 \
            v[j1_] = fma2(t2,  a0,   v[j1_]);                               \
        }                                                                   \
    }

__global__ __launch_bounds__(THREADS, 4)
void qc_kernel(const float* __restrict__ x,
               const float* __restrict__ th,
               float* __restrict__ out)
{
    __shared__ ull st2[STSZ];
    __shared__ ull enc_c[NQ], enc_s[NQ];    // packed (item0, item1)
    __shared__ ull th_t2[2][NQ];            // packed (tan, tan)
    __shared__ float cosv[2 * NQ];
    __shared__ ull red[(THREADS / 32) * NQ];

    const int b    = blockIdx.x;            // batch items 2b, 2b+1
    const int t    = threadIdx.x;
    const int lane = t & 31;

    // ownership bases, pad M(e) = e + (e>>4); all phases conflict-free (derived above)
    const int baseA = 17 * t;                              // + j        (e = 16t + j)
    const int baseC = (t & 15) + 272 * (t >> 4);           // + 17*j     (e = (t&15)|(j<<4)|((t>>4)<<8))
    const int baseB = t + (t >> 4);                        // + 272*j    (e = (j<<8) | t)

    // ---- angle precompute ----
    if (t < NQ) {
        float c0, s0, c1, s1;
        sincosf(0.5f * x[(2 * b) * NQ + t],     &s0, &c0);
        sincosf(0.5f * x[(2 * b + 1) * NQ + t], &s1, &c1);
        enc_c[t] = pk(c0, c1);
        enc_s[t] = pk(s0, s1);
    } else if (t >= 32 && t < 32 + 2 * NQ) {
        int k = t - 32;                     // layer*12 + q
        float s_, c_;
        sincosf(0.5f * th[k], &s_, &c_);
        float tg = s_ / c_;
        th_t2[k / NQ][k % NQ] = pk(tg, tg);
        cosv[k] = c_;
    }
    __syncthreads();

    // ---- packed product state, ownership A: e = 16t + j ----
    // e bits 0-3 = j -> qubits 0-3 ; t bits 0-7 -> qubits 4-11
    ull v[NREG];
    {
        ull h = (t & 1) ? enc_s[4] : enc_c[4];
        #pragma unroll
        for (int i = 1; i < 8; i++)
            h = mul2(h, ((t >> i) & 1) ? enc_s[4 + i] : enc_c[4 + i]);
        ull lo[4], hi[4];
        #pragma unroll
        for (int m = 0; m < 4; m++) {
            lo[m] = mul2((m & 1) ? enc_s[0] : enc_c[0], (m & 2) ? enc_s[1] : enc_c[1]);
            hi[m] = mul2((m & 1) ? enc_s[2] : enc_c[2], (m & 2) ? enc_s[3] : enc_c[3]);
        }
        #pragma unroll
        for (int j = 0; j < NREG; j++)
            v[j] = mul2(mul2(h, lo[j & 3]), hi[j >> 2]);
    }

    // scatter constants: prefix-xor of t's 8 bits
    unsigned yt = (unsigned)t; yt ^= yt << 1; yt ^= yt << 2; yt ^= yt << 4;
    const int pt  = (yt >> 7) & 1;                         // parity(t)
    const int Zt  = t ^ (int)((yt << 1) & 0x1FE);          // t-part of dst
    const int ptm = pt ? 15 : 0;

    // ---- variational layers (tan-form, cosines deferred) ----
    #pragma unroll
    for (int layer = 0; layer < 2; layer++) {
        const ull* T = th_t2[layer];

        XGATE(T[0], 0) XGATE(T[1], 1) XGATE(T[2], 2) XGATE(T[3], 3)   // q0-3 (A)

        #pragma unroll
        for (int j = 0; j < NREG; j++) st2[baseA + j] = v[j];
        __syncthreads();
        #pragma unroll
        for (int j = 0; j < NREG; j++) v[j] = st2[baseC + 17 * j];

        XGATE(T[4], 0) XGATE(T[5], 1) XGATE(T[6], 2) XGATE(T[7], 3)   // q4-7 (C)

        #pragma unroll
        for (int j = 0; j < NREG; j++) st2[baseC + 17 * j] = v[j];
        __syncthreads();
        #pragma unroll
        for (int j = 0; j < NREG; j++) v[j] = st2[baseB + 272 * j];

        XGATE(T[8], 0) XGATE(T[9], 1) XGATE(T[10], 2) XGATE(T[11], 3) // q8-11 (B)

        if (layer == 0) {
            // CNOT ring: dst = e ^ ((px<<1)&0xFFE) ^ (px>>11), e = (j<<8)|t
            // px = PXT | ((PXJ(j) ^ pt*15) << 8)
            __syncthreads();                               // all B reads done
            #pragma unroll
            for (int j = 0; j < NREG; j++) {
                const int j0 = j & 1, j1 = (j >> 1) & 1, j2 = (j >> 2) & 1, j3 = (j >> 3) & 1;
                const int PXJ = j0 | ((j0 ^ j1) << 1) | ((j0 ^ j1 ^ j2) << 2)
                              | ((j0 ^ j1 ^ j2 ^ j3) << 3);
                const int ph  = PXJ ^ ptm;
                int dst = Zt ^ (j << 8) ^ ((ph & 7) << 9) ^ (ph >> 3);
                st2[dst + (dst >> 4)] = v[j];
            }
            __syncthreads();
            #pragma unroll
            for (int j = 0; j < NREG; j++) v[j] = st2[baseA + j];
        }
        // layer 1: trailing ring folded into expectation signs
    }

    // ---- expectations in B-ownership (e = 256j + t), R12-verified signs, packed ----
    ull P = 0, g1 = 0, g3 = 0, g7 = 0, gF = 0;
    #pragma unroll
    for (int j = 0; j < NREG; j++) {
        ull p  = mul2(v[j], v[j]);
        ull np = p ^ SGN2;
        P  = add2(P, p);
        g1 = add2(g1, (__popc(j & 1)  & 1) ? np : p);
        g3 = add2(g3, (__popc(j & 3)  & 1) ? np : p);
        g7 = add2(g7, (__popc(j & 7)  & 1) ? np : p);
        gF = add2(gF, (__popc(j & 15) & 1) ? np : p);
    }
    const int pt1 = __popc(t >> 1) & 1;

    ull acc[NQ];
    acc[0] = pt1 ? (gF ^ SGN2) : gF;
    #pragma unroll
    for (int q = 1; q < 8; q++) {
        int sq = __popc(t & ((1 << (q + 1)) - 1)) & 1;
        acc[q] = sq ? (P ^ SGN2) : P;
    }
    acc[8]  = pt ? (g1 ^ SGN2) : g1;
    acc[9]  = pt ? (g3 ^ SGN2) : g3;
    acc[10] = pt ? (g7 ^ SGN2) : g7;
    acc[11] = pt ? (gF ^ SGN2) : gF;

    #pragma unroll
    for (int q = 0; q < NQ; q++) {
        #pragma unroll
        for (int off = 16; off; off >>= 1)
            acc[q] = add2(acc[q], __shfl_down_sync(0xFFFFFFFFu, acc[q], off));
    }
    const int w = t >> 5;
    if (lane == 0) {
        #pragma unroll
        for (int q = 0; q < NQ; q++) red[w * NQ + q] = acc[q];
    }
    __syncthreads();
    if (t < NQ) {
        ull r = red[t];
        #pragma unroll
        for (int w2 = 1; w2 < THREADS / 32; w2++) r = add2(r, red[w2 * NQ + t]);
        float cs = cosv[0];
        #pragma unroll
        for (int k = 1; k < 2 * NQ; k++) cs *= cosv[k];
        const float sc2 = cs * cs;
        float r0, r1; upk(r, r0, r1);
        out[(2 * b) * NQ + t]     = r0 * sc2;
        out[(2 * b + 1) * NQ + t] = r1 * sc2;
    }
}

extern "C" void kernel_launch(void* const* d_in, const int* in_sizes, int n_in,
                              void* d_out, int out_size)
{
    const float* x  = (const float*)d_in[0];   // (1024, 12) float32
    const float* th = (const float*)d_in[1];   // (2, 12)    float32
    float* o = (float*)d_out;                  // (1024, 12) float32
    (void)in_sizes; (void)n_in; (void)out_size;
    qc_kernel<<<512, THREADS>>>(x, th, o);
}

// round 17
// speedup vs baseline: 1.0703x; 1.0449x over previous
#include <cuda_runtime.h>

#define NQ      12
#define DIM     4096
#define THREADS 256
#define EPT     16
#define STSZ    4224        // scalar padded layout: addr = s + (s>>5), max 4222

// tan-form RY butterfly (deferred cosine): a0' = a0 - t*a1 ; a1' = a1 + t*a0
#define REG_BF4T(TT, QBASE)                                                \
    _Pragma("unroll")                                                      \
    for (int rb = 0; rb < 4; rb++) {                                       \
        const float tg = (TT)[(QBASE) + rb];                               \
        _Pragma("unroll")                                                  \
        for (int m = 0; m < 8; m++) {                                      \
            const int low = (1 << rb) - 1;                                 \
            const int j0  = ((m & ~low) << 1) | (m & low);                 \
            const int j1  = j0 | (1 << rb);                                \
            float a0 = v[j0];                                              \
            v[j0] = fmaf(-tg, v[j1], a0);                                  \
            v[j1] = fmaf( tg, a0,   v[j1]);                                \
        }                                                                  \
    }

// 5-step lane Hadamard: after this, lane L holds sum_l (-1)^{popc(l&L)} x_l
#define WHT5(xv)                                                           \
    _Pragma("unroll")                                                      \
    for (int k = 1; k <= 16; k <<= 1) {                                    \
        float o_ = __shfl_xor_sync(0xFFFFFFFFu, (xv), k);                  \
        (xv) = (lane & k) ? (o_ - (xv)) : (o_ + (xv));                     \
    }

__global__ __launch_bounds__(THREADS, 7)
void qc_kernel(const float* __restrict__ x,
               const float* __restrict__ th,
               float* __restrict__ out)
{
    __shared__ float st[STSZ];
    __shared__ float enc_c[NQ], enc_s[NQ];
    __shared__ float th_t[2][NQ];
    __shared__ float cosv[2 * NQ];
    __shared__ float red[(THREADS / 32) * NQ];

    const int b    = blockIdx.x;
    const int tid  = threadIdx.x;
    const int lane = tid & 31;
    const int w    = tid >> 5;

    // padded bases: addr = s + (s>>5) (R4/R12-verified conflict-free for A/B/C)
    const int baseA = tid * 16 + (tid >> 1);                 // + j
    const int baseB = tid + (tid >> 5);                      // + 264*j
    const int tb    = ((tid >> 5) & 1) | (((tid >> 4) & 1) << 1)
                    | (((tid >> 6) & 1) << 2) | (((tid >> 7) & 1) << 3);
    const int baseC = (tid & 15) + 264 * tb;                 // + 16*j + (j>>1)

    // ---- angle precompute across 2 warps ----
    if (tid < NQ) {
        float s_, c_;
        sincosf(0.5f * x[b * NQ + tid], &s_, &c_);
        enc_c[tid] = c_; enc_s[tid] = s_;
    } else if (tid >= 32 && tid < 32 + 2 * NQ) {
        int k = tid - 32;                 // layer*12 + q
        float s_, c_;
        sincosf(0.5f * th[k], &s_, &c_);
        th_t[k / NQ][k % NQ] = s_ / c_;
        cosv[k] = c_;
    }
    __syncthreads();

    // ---- product state in registers (ownership A: s = 16*tid + j) ----
    float v[EPT];
    {
        float h = (tid & 1) ? enc_s[4] : enc_c[4];
        #pragma unroll
        for (int i = 1; i < 8; i++)
            h *= ((tid >> i) & 1) ? enc_s[4 + i] : enc_c[4 + i];
        float lo[4], hi[4];
        #pragma unroll
        for (int m = 0; m < 4; m++) {
            lo[m] = ((m & 1) ? enc_s[0] : enc_c[0]) * ((m & 2) ? enc_s[1] : enc_c[1]);
            hi[m] = ((m & 1) ? enc_s[2] : enc_c[2]) * ((m & 2) ? enc_s[3] : enc_c[3]);
        }
        #pragma unroll
        for (int j = 0; j < EPT; j++)
            v[j] = h * lo[j & 3] * hi[j >> 2];
    }

    // ---- variational layers (tan-form gates, cosines deferred) ----
    #pragma unroll
    for (int layer = 0; layer < 2; layer++) {
        const float* T = th_t[layer];

        REG_BF4T(T, 0)                          // qubits 0-3 (A)

        #pragma unroll
        for (int j = 0; j < EPT; j++) st[baseA + j] = v[j];
        __syncthreads();
        #pragma unroll
        for (int j = 0; j < EPT; j++) v[j] = st[baseC + 16 * j + (j >> 1)];

        REG_BF4T(T, 4)                          // qubits 4-7 (C)

        #pragma unroll
        for (int j = 0; j < EPT; j++) st[baseC + 16 * j + (j >> 1)] = v[j];
        __syncthreads();
        #pragma unroll
        for (int j = 0; j < EPT; j++) v[j] = st[baseB + 264 * j];

        REG_BF4T(T, 8)                          // qubits 8-11 (B)

        if (layer == 0) {
            // CNOT ring = bit-linear permutation; scatter B -> gather A
            unsigned px = tid; px ^= px << 1; px ^= px << 2; px ^= px << 4;
            const int Pt  = (px >> 7) & 1;
            const int Tt  = (tid ^ (int)(px << 1)) & 0xFE;
            const int t0p = (tid & 1) ^ Pt;
            const int pb0 = Tt + t0p       + (Tt >> 5);
            const int pb1 = Tt + (t0p ^ 1) + (Tt >> 5);
            const int msk = Pt ? 15 : 0;

            __syncthreads();                    // all B reads done before scatter
            #pragma unroll
            for (int j = 0; j < EPT; j++) {
                const int j0 = j & 1, j1 = (j >> 1) & 1, j2 = (j >> 2) & 1, j3 = (j >> 3) & 1;
                const int Jv = j0 | ((j1 ^ j0) << 1) | ((j2 ^ j1 ^ j0) << 2)
                             | ((j3 ^ j2 ^ j1 ^ j0) << 3);
                const int pj = j0 ^ j1 ^ j2 ^ j3;
                st[(pj ? pb1 : pb0) + 264 * (Jv ^ msk)] = v[j];
            }
            __syncthreads();
            #pragma unroll
            for (int j = 0; j < EPT; j++) v[j] = st[baseA + j];
        }
        // layer 1: ring permutation folded into expectation signs
    }

    // ---- epilogue: Walsh tree over j + lane-Hadamard over the warp ----
    // bases (R12-verified sign sets): P, g1(mask1), g3(mask3), g7(mask7), gF(mask15)
    float P, g1, g3, g7, gF;
    {
        float p[EPT];
        #pragma unroll
        for (int j = 0; j < EPT; j++) p[j] = v[j] * v[j];
        float a[8], d[8];
        #pragma unroll
        for (int i = 0; i < 8; i++) { a[i] = p[2*i] + p[2*i+1]; d[i] = p[2*i] - p[2*i+1]; }
        P = ((a[0] + a[1]) + (a[2] + a[3])) + ((a[4] + a[5]) + (a[6] + a[7]));
        float u[4], e[4];
        #pragma unroll
        for (int i = 0; i < 4; i++) { u[i] = d[2*i] + d[2*i+1]; e[i] = d[2*i] - d[2*i+1]; }
        g1 = (u[0] + u[1]) + (u[2] + u[3]);
        g3 = (e[0] + e[1]) + (e[2] + e[3]);
        float x0 = e[0] - e[1], x1 = e[2] - e[3];
        g7 = x0 + x1;
        gF = x0 - x1;
    }

    WHT5(P) WHT5(g1) WHT5(g3) WHT5(g7) WHT5(gF)

    // warp-bit sign constants
    const int pw = __popc(w) & 1;          // parity of all 3 warp bits
    const int b1 = w & 1;
    const int b3 = __popc(w & 3) & 1;

    // lane L of WHT(base) = warp-partial with lane-sign mask L; add warp signs and stash
    if (lane == 3)  red[w * NQ + 1] = P;                    // q1: mask 3
    if (lane == 7)  red[w * NQ + 2] = P;                    // q2: mask 7
    if (lane == 15) red[w * NQ + 3] = P;                    // q3: mask 15
    if (lane == 30) red[w * NQ + 0] = pw ? -gF : gF;        // q0: mask 30 + parity(w)
    if (lane == 31) {
        red[w * NQ + 4]  = P;                               // q4: mask 31
        red[w * NQ + 5]  = b1 ? -P : P;                     // q5: + w bit0
        red[w * NQ + 6]  = b3 ? -P : P;                     // q6: + w bits 0-1
        red[w * NQ + 7]  = pw ? -P : P;                     // q7: + w bits 0-2
        red[w * NQ + 8]  = pw ? -g1 : g1;                   // q8
        red[w * NQ + 9]  = pw ? -g3 : g3;                   // q9
        red[w * NQ + 10] = pw ? -g7 : g7;                   // q10
        red[w * NQ + 11] = pw ? -gF : gF;                   // q11
    }
    __syncthreads();
    if (tid < NQ) {
        float r = 0.0f;
        #pragma unroll
        for (int w2 = 0; w2 < THREADS / 32; w2++) r += red[w2 * NQ + tid];
        // deferred cosine scale: out *= (prod_{24 gates} cos)^2
        float cs = cosv[0];
        #pragma unroll
        for (int k = 1; k < 2 * NQ; k++) cs *= cosv[k];
        out[b * NQ + tid] = r * cs * cs;
    }
}

extern "C" void kernel_launch(void* const* d_in, const int* in_sizes, int n_in,
                              void* d_out, int out_size)
{
    const float* x  = (const float*)d_in[0];   // (1024, 12) float32
    const float* th = (const float*)d_in[1];   // (2, 12)    float32
    float* o = (float*)d_out;                  // (1024, 12) float32
    (void)in_sizes; (void)n_in; (void)out_size;
    qc_kernel<<<1024, THREADS>>>(x, th, o);
}